// round 2
// baseline (speedup 1.0000x reference)
#include <cuda_runtime.h>
#include <cstdint>

// Problem constants
#define B_SZ   256
#define T_SZ   2049
#define D_SZ   64
#define H_SZ   64
#define MLP_SZ 128
#define NI_SZ  128
#define OUT_SZ 10
#define L_SZ   2080
#define S_SZ   16
#define BN_TOT 32768          // B_SZ * NI_SZ
#define NB_PAD 8320           // 8192 (W2 rows) + 64 (b2 rows) + 64 pad -> 65 tiles of 128
#define KD     2080

// Scratch (device globals; allocation-free)
__device__ float g_ls[(size_t)BN_TOT * L_SZ];     // 272.6 MB : logsig (fp32)
__device__ float g_B [(size_t)NB_PAD * KD];       //  69.2 MB : [W2; b2; 0] (fp32)
__device__ float g_V [(size_t)BN_TOT * NB_PAD];   //   1.09 GB : V = ls @ B^T

__device__ __forceinline__ uint32_t tf32u(float x) {
    uint32_t u;
    asm("cvt.rna.tf32.f32 %0, %1;" : "=r"(u) : "f"(x));
    return u;
}

// ---------------------------------------------------------------------------
// Kernel 0: build B matrix = [W2 (8192 rows); b2 (64 rows); zeros (64 rows)].
// W2[m, d*L + l] is at (m*64+d)*2080 + l, so rows 0..8191 are a flat W2 copy.
// ---------------------------------------------------------------------------
__global__ void prep_B_k(const float* __restrict__ W2, const float* __restrict__ b2) {
    int r = blockIdx.x;
    float* dst = g_B + (size_t)r * KD;
    const float* src = nullptr;
    if (r < 8192)       src = W2 + (size_t)r * KD;
    else if (r < 8256)  src = b2 + (size_t)(r - 8192) * KD;
    for (int l = threadIdx.x; l < KD; l += blockDim.x)
        dst[l] = src ? src[l] : 0.0f;
}

// ---------------------------------------------------------------------------
// Kernel 1: depth-2 log-signature per (b, n).
// ls[bn, 0:64]   = seg[16] - seg[0]
// ls[bn, 64+p]   = 0.5*(M[i][j] - M[j][i]),  M = cum^T dlt,  p -> (i<j) row-major
// ---------------------------------------------------------------------------
__global__ void logsig_k(const float* __restrict__ X) {
    __shared__ float seg[17 * 64];
    __shared__ float cumS[16 * 64];
    __shared__ float dltS[16 * 64];
    __shared__ float Ms[64 * 64];

    int n = blockIdx.x, b = blockIdx.y;
    int bn = b * NI_SZ + n;
    int t = threadIdx.x;

    const float4* xp4 = (const float4*)(X + ((size_t)b * T_SZ + (size_t)n * S_SZ) * D_SZ);
    float4* seg4 = (float4*)seg;
    for (int i = t; i < 17 * 64 / 4; i += 256) seg4[i] = xp4[i];
    __syncthreads();

    for (int i = t; i < 16 * 64; i += 256) {
        int k = i >> 6, d = i & 63;
        cumS[i] = seg[k * 64 + d] - seg[d];
        dltS[i] = seg[(k + 1) * 64 + d] - seg[k * 64 + d];
    }
    __syncthreads();

    if (t < 64)
        g_ls[(size_t)bn * L_SZ + t] = seg[16 * 64 + t] - seg[t];

    // M[i][j] = sum_k cum[k][i] * dlt[k][j]; thread t owns (i = t>>2, 16 cols)
    {
        int i = t >> 2;
        int jb = (t & 3) * 16;
        float acc[16];
        #pragma unroll
        for (int q = 0; q < 16; ++q) acc[q] = 0.0f;
        #pragma unroll
        for (int k = 0; k < 16; ++k) {
            float ci = cumS[k * 64 + i];
            const float4* dl4 = (const float4*)(dltS + k * 64 + jb);
            #pragma unroll
            for (int q4 = 0; q4 < 4; ++q4) {
                float4 dv = dl4[q4];
                acc[q4 * 4 + 0] += ci * dv.x;
                acc[q4 * 4 + 1] += ci * dv.y;
                acc[q4 * 4 + 2] += ci * dv.z;
                acc[q4 * 4 + 3] += ci * dv.w;
            }
        }
        float4* mrow = (float4*)(Ms + i * 64 + jb);
        #pragma unroll
        for (int q4 = 0; q4 < 4; ++q4)
            mrow[q4] = make_float4(acc[q4 * 4 + 0], acc[q4 * 4 + 1],
                                   acc[q4 * 4 + 2], acc[q4 * 4 + 3]);
    }
    __syncthreads();

    // Upper-triangular pairs, row-major (i, j) with i < j
    for (int p = t; p < 2016; p += 256) {
        int i = 0, rs = 0;
        while (rs + (63 - i) <= p) { rs += 63 - i; ++i; }
        int j = i + 1 + (p - rs);
        float a = 0.5f * (Ms[i * 64 + j] - Ms[j * 64 + i]);
        g_ls[(size_t)bn * L_SZ + 64 + p] = a;
    }
}

// ---------------------------------------------------------------------------
// Kernel 2: TN GEMM  g_V[32768, 8320] = g_ls[32768, 2080] @ g_B[8320, 2080]^T
// 3xTF32 error-compensated: x = hi + lo (each tf32); c += ah*bh + al*bh + ah*bl.
// mma.sync m16n8k8 tf32, fp32 accumulate. CTA tile 128x128x32, 8 warps (2x4),
// warp tile 64x32, cp.async double-buffered smem.
// ---------------------------------------------------------------------------
#define BM  128
#define BN  128
#define BK  32
#define BKP 36   // pad: conflict-free scalar frag loads

__device__ __forceinline__ void cp16(void* s, const void* g) {
    uint32_t sa = (uint32_t)__cvta_generic_to_shared(s);
    asm volatile("cp.async.cg.shared.global [%0], [%1], 16;" :: "r"(sa), "l"(g));
}
__device__ __forceinline__ void cp_commit() {
    asm volatile("cp.async.commit_group;");
}
__device__ __forceinline__ void cp_wait0() {
    asm volatile("cp.async.wait_group 0;");
}
__device__ __forceinline__ void mma_tf32(float* c, const uint32_t* a, const uint32_t* b) {
    asm volatile(
        "mma.sync.aligned.m16n8k8.row.col.f32.tf32.tf32.f32 "
        "{%0,%1,%2,%3}, {%4,%5,%6,%7}, {%8,%9}, {%0,%1,%2,%3};"
        : "+f"(c[0]), "+f"(c[1]), "+f"(c[2]), "+f"(c[3])
        : "r"(a[0]), "r"(a[1]), "r"(a[2]), "r"(a[3]), "r"(b[0]), "r"(b[1]));
}
// split float -> (hi, lo) tf32 pair
__device__ __forceinline__ void split32(float v, uint32_t& hi, uint32_t& lo) {
    hi = tf32u(v);
    lo = tf32u(v - __uint_as_float(hi));
}

__global__ void __launch_bounds__(256, 1) gemm_k() {
    extern __shared__ float sm[];
    float* As = sm;                         // [2][BM][BKP]
    float* Bs = sm + 2 * BM * BKP;          // [2][BN][BKP]

    int tid  = threadIdx.x;
    int lane = tid & 31;
    int wid  = tid >> 5;
    int gid  = lane >> 2;
    int tig  = lane & 3;
    int wm   = (wid & 1) * 64;
    int wn   = (wid >> 1) * 32;
    int mtile = blockIdx.y, ntile = blockIdx.x;

    const float* Ag = g_ls + (size_t)(mtile * BM) * KD;
    const float* Bg = g_B  + (size_t)(ntile * BN) * KD;

    float c[4][4][4];
    #pragma unroll
    for (int mi = 0; mi < 4; ++mi)
        #pragma unroll
        for (int ni = 0; ni < 4; ++ni)
            #pragma unroll
            for (int q = 0; q < 4; ++q) c[mi][ni][q] = 0.0f;

    int lr = tid >> 3;        // 0..31 row within 32-row wave
    int lc = (tid & 7) * 4;   // col (floats), 16B chunk

    auto stage = [&](int kb, int buf) {
        float* Ad = As + buf * BM * BKP;
        float* Bd = Bs + buf * BN * BKP;
        #pragma unroll
        for (int rr = 0; rr < BM; rr += 32) {
            cp16(&Ad[(lr + rr) * BKP + lc], Ag + (size_t)(lr + rr) * KD + kb + lc);
            cp16(&Bd[(lr + rr) * BKP + lc], Bg + (size_t)(lr + rr) * KD + kb + lc);
        }
    };

    stage(0, 0);
    cp_commit();

    const int nk = KD / BK;   // 65, exact
    for (int it = 0; it < nk; ++it) {
        cp_wait0();
        __syncthreads();
        if (it + 1 < nk) { stage((it + 1) * BK, (it + 1) & 1); cp_commit(); }

        const float* Ab = As + (it & 1) * BM * BKP;
        const float* Bb = Bs + (it & 1) * BN * BKP;

        #pragma unroll
        for (int ks = 0; ks < 4; ++ks) {
            int k0 = ks * 8;
            uint32_t ah[4][4], al[4][4], bh[4][2], bl[4][2];
            #pragma unroll
            for (int mi = 0; mi < 4; ++mi) {
                int row = wm + mi * 16 + gid;
                split32(Ab[row * BKP + k0 + tig],           ah[mi][0], al[mi][0]);
                split32(Ab[(row + 8) * BKP + k0 + tig],     ah[mi][1], al[mi][1]);
                split32(Ab[row * BKP + k0 + tig + 4],       ah[mi][2], al[mi][2]);
                split32(Ab[(row + 8) * BKP + k0 + tig + 4], ah[mi][3], al[mi][3]);
            }
            #pragma unroll
            for (int ni = 0; ni < 4; ++ni) {
                int rn = wn + ni * 8 + gid;
                split32(Bb[rn * BKP + k0 + tig],     bh[ni][0], bl[ni][0]);
                split32(Bb[rn * BKP + k0 + tig + 4], bh[ni][1], bl[ni][1]);
            }
            #pragma unroll
            for (int mi = 0; mi < 4; ++mi)
                #pragma unroll
                for (int ni = 0; ni < 4; ++ni) {
                    mma_tf32(c[mi][ni], al[mi], bh[ni]);   // lo*hi
                    mma_tf32(c[mi][ni], ah[mi], bl[ni]);   // hi*lo
                    mma_tf32(c[mi][ni], ah[mi], bh[ni]);   // hi*hi
                }
        }
    }

    // Epilogue: fp32 stores, adjacent-column float2
    int rowbase = mtile * BM + wm;
    int colbase = ntile * BN + wn;
    #pragma unroll
    for (int mi = 0; mi < 4; ++mi) {
        #pragma unroll
        for (int ni = 0; ni < 4; ++ni) {
            int r0 = rowbase + mi * 16 + gid;
            int cc = colbase + ni * 8 + tig * 2;
            float2 v0 = make_float2(c[mi][ni][0], c[mi][ni][1]);
            float2 v1 = make_float2(c[mi][ni][2], c[mi][ni][3]);
            *(float2*)&g_V[(size_t)r0 * NB_PAD + cc]       = v0;
            *(float2*)&g_V[(size_t)(r0 + 8) * NB_PAD + cc] = v1;
        }
    }
}

// ---------------------------------------------------------------------------
// Kernel 3: RK4 scan. One CTA per batch element, 128 threads.
// Per interval: load V slice [129 x 64] (row 128 = bias term c), then 4 stages:
//   z_j = tanh(sum_i ht[i] W1[i][j] + b1[j]),  k_d = sum_m z[m] V[m][d] + c[d]
// ---------------------------------------------------------------------------
__global__ void __launch_bounds__(128) scan_k(
    const float* __restrict__ X,    const float* __restrict__ W_in,
    const float* __restrict__ b_in, const float* __restrict__ W1,
    const float* __restrict__ b1,   const float* __restrict__ W_out,
    const float* __restrict__ b_out, float* __restrict__ out)
{
    __shared__ float Vs[129 * 64];    // 33 KB
    __shared__ float h[64], ht[64], z[128], ksum[64];

    int b = blockIdx.x;
    int t = threadIdx.x;

    // W1 column t in registers
    float w1r[64];
    #pragma unroll
    for (int i = 0; i < 64; ++i) w1r[i] = W1[i * 128 + t];
    float b1t = b1[t];

    if (t < 64) {
        float acc = b_in[t];
        const float* x0 = X + (size_t)b * T_SZ * D_SZ;
        #pragma unroll
        for (int d = 0; d < 64; ++d) acc += x0[d] * W_in[d * 64 + t];
        h[t] = acc; ht[t] = acc; ksum[t] = 0.0f;
    }
    __syncthreads();

    const float wgt[4] = {1.0f, 2.0f, 2.0f, 1.0f};
    const float aco[4] = {0.5f, 0.5f, 1.0f, 0.0f};

    for (int n = 0; n < NI_SZ; ++n) {
        const float4* vg = (const float4*)(g_V + (size_t)(b * NI_SZ + n) * NB_PAD);
        float4* vs4 = (float4*)Vs;
        for (int c4 = t; c4 < (129 * 64) / 4; c4 += 128) vs4[c4] = vg[c4];
        __syncthreads();

        #pragma unroll
        for (int s = 0; s < 4; ++s) {
            float acc = b1t;
            #pragma unroll
            for (int i = 0; i < 64; ++i) acc += ht[i] * w1r[i];
            z[t] = tanhf(acc);
            __syncthreads();
            if (t < 64) {
                float ka = Vs[128 * 64 + t];
                #pragma unroll
                for (int m = 0; m < 128; ++m) ka += z[m] * Vs[m * 64 + t];
                ksum[t] += wgt[s] * ka;
                if (s < 3) ht[t] = h[t] + aco[s] * ka;
            }
            __syncthreads();
        }
        if (t < 64) {
            float hn = h[t] + ksum[t] * (1.0f / 6.0f);
            h[t] = hn; ht[t] = hn; ksum[t] = 0.0f;
        }
        __syncthreads();
    }

    if (t < OUT_SZ) {
        float acc = b_out[t];
        #pragma unroll
        for (int d = 0; d < 64; ++d) acc += h[d] * W_out[d * OUT_SZ + t];
        out[b * OUT_SZ + t] = acc;
    }
}

// ---------------------------------------------------------------------------
extern "C" void kernel_launch(void* const* d_in, const int* in_sizes, int n_in,
                              void* d_out, int out_size) {
    const float* X     = (const float*)d_in[0];
    const float* W_in  = (const float*)d_in[1];
    const float* b_in  = (const float*)d_in[2];
    const float* W1    = (const float*)d_in[3];
    const float* b1    = (const float*)d_in[4];
    const float* W2    = (const float*)d_in[5];
    const float* b2    = (const float*)d_in[6];
    const float* W_out = (const float*)d_in[7];
    const float* b_out = (const float*)d_in[8];
    float* out = (float*)d_out;

    (void)in_sizes; (void)n_in; (void)out_size;

    size_t gemm_smem = (size_t)2 * (BM + BN) * BKP * sizeof(float);  // 73728 B
    cudaFuncSetAttribute(gemm_k, cudaFuncAttributeMaxDynamicSharedMemorySize,
                         (int)gemm_smem);

    prep_B_k<<<NB_PAD, 256>>>(W2, b2);
    logsig_k<<<dim3(NI_SZ, B_SZ), 256>>>(X);
    gemm_k<<<dim3(NB_PAD / BN, BN_TOT / BM), 256, gemm_smem>>>();
    scan_k<<<B_SZ, 128>>>(X, W_in, b_in, W1, b1, W_out, b_out, out);
}

// round 4
// speedup vs baseline: 3.6573x; 3.6573x over previous
#include <cuda_runtime.h>
#include <cuda_fp16.h>
#include <cstdint>

// Problem constants
#define B_SZ   256
#define T_SZ   2049
#define D_SZ   64
#define H_SZ   64
#define MLP_SZ 128
#define NI_SZ  128
#define OUT_SZ 10
#define L_SZ   2080
#define S_SZ   16
#define BN_TOT 32768          // GEMM M
#define NBP    8320           // GEMM N: 8192 (W2) + 64 (b2) + 64 zero -> 65 tiles of 128
#define KD     2080           // GEMM K: 65 iters of 32
#define BM     128
#define BN     128
#define BK     32
#define NKIT   (KD / BK)      // 65
#define STAGE_B 32768         // A(16KB: 128 rows x [hi64B|lo64B]) + B(16KB)

// Scratch (device globals; allocation-free)
__device__ __half g_ls_hi[(size_t)BN_TOT * KD];   // 136 MB
__device__ __half g_ls_lo[(size_t)BN_TOT * KD];   // 136 MB
__device__ __half g_B_hi [(size_t)NBP * KD];      // 34.6 MB
__device__ __half g_B_lo [(size_t)NBP * KD];      // 34.6 MB
__device__ float  g_V    [(size_t)BN_TOT * NBP];  // 1.09 GB

__device__ __forceinline__ void hsplit(float v, __half& h, __half& l) {
    h = __float2half_rn(v);
    l = __float2half_rn(v - __half2float(h));
}

// ---------------------------------------------------------------------------
// Kernel 0: B rows = [W2 flat (8192); b2 (64); zeros (64)], fp16 hi/lo.
// W2[m, d*L+l] at (m*64+d)*2080+l -> rows 0..8191 are a flat W2 copy.
// ---------------------------------------------------------------------------
__global__ void prep_B_k(const float* __restrict__ W2, const float* __restrict__ b2) {
    int r = blockIdx.x;
    const float* src = nullptr;
    if (r < 8192)       src = W2 + (size_t)r * L_SZ;
    else if (r < 8256)  src = b2 + (size_t)(r - 8192) * L_SZ;
    size_t o = (size_t)r * KD;
    for (int l = threadIdx.x; l < KD; l += blockDim.x) {
        float v = src ? src[l] : 0.0f;
        __half h, lo;
        hsplit(v, h, lo);
        g_B_hi[o + l] = h;
        g_B_lo[o + l] = lo;
    }
}

// ---------------------------------------------------------------------------
// Kernel 1: depth-2 log-signature per (b, n), fp16 hi/lo output.
// ---------------------------------------------------------------------------
__global__ void logsig_k(const float* __restrict__ X) {
    __shared__ float seg[17 * 64];
    __shared__ float cumS[16 * 64];
    __shared__ float dltS[16 * 64];
    __shared__ float Ms[64 * 64];

    int n = blockIdx.x, b = blockIdx.y;
    size_t bno = (size_t)(b * NI_SZ + n) * KD;
    int t = threadIdx.x;

    const float4* xp4 = (const float4*)(X + ((size_t)b * T_SZ + (size_t)n * S_SZ) * D_SZ);
    float4* seg4 = (float4*)seg;
    for (int i = t; i < 17 * 64 / 4; i += 256) seg4[i] = xp4[i];
    __syncthreads();

    for (int i = t; i < 16 * 64; i += 256) {
        int k = i >> 6, d = i & 63;
        cumS[i] = seg[k * 64 + d] - seg[d];
        dltS[i] = seg[(k + 1) * 64 + d] - seg[k * 64 + d];
    }
    __syncthreads();

    if (t < 64) {
        __half h, lo;
        hsplit(seg[16 * 64 + t] - seg[t], h, lo);
        g_ls_hi[bno + t] = h; g_ls_lo[bno + t] = lo;
    }

    // M[i][j] = sum_k cum[k][i] * dlt[k][j]; thread t owns (i = t>>2, 16 cols)
    {
        int i = t >> 2;
        int jb = (t & 3) * 16;
        float acc[16];
        #pragma unroll
        for (int q = 0; q < 16; ++q) acc[q] = 0.0f;
        #pragma unroll
        for (int k = 0; k < 16; ++k) {
            float ci = cumS[k * 64 + i];
            const float4* dl4 = (const float4*)(dltS + k * 64 + jb);
            #pragma unroll
            for (int q4 = 0; q4 < 4; ++q4) {
                float4 dv = dl4[q4];
                acc[q4 * 4 + 0] += ci * dv.x;
                acc[q4 * 4 + 1] += ci * dv.y;
                acc[q4 * 4 + 2] += ci * dv.z;
                acc[q4 * 4 + 3] += ci * dv.w;
            }
        }
        float4* mrow = (float4*)(Ms + i * 64 + jb);
        #pragma unroll
        for (int q4 = 0; q4 < 4; ++q4)
            mrow[q4] = make_float4(acc[q4 * 4 + 0], acc[q4 * 4 + 1],
                                   acc[q4 * 4 + 2], acc[q4 * 4 + 3]);
    }
    __syncthreads();

    for (int p = t; p < 2016; p += 256) {
        int i = 0, rs = 0;
        while (rs + (63 - i) <= p) { rs += 63 - i; ++i; }
        int j = i + 1 + (p - rs);
        float a = 0.5f * (Ms[i * 64 + j] - Ms[j * 64 + i]);
        __half h, lo;
        hsplit(a, h, lo);
        g_ls_hi[bno + 64 + p] = h; g_ls_lo[bno + 64 + p] = lo;
    }
}

// ---------------------------------------------------------------------------
// Kernel 2: TN GEMM  g_V = ls @ B^T via mma.sync.m16n8k16.f16 (fp32 accum),
// 3-product fp16 split (ah*bh + al*bh + ah*bl). CTA 128x128x32, 8 warps (2x4),
// warp tile 64x32. SW128 smem rows = [hi 64B | lo 64B]. cp.async dbl-buffer.
// ---------------------------------------------------------------------------
__device__ __forceinline__ void cp16s(uint32_t saddr, const void* g) {
    asm volatile("cp.async.cg.shared.global [%0], [%1], 16;" :: "r"(saddr), "l"(g));
}
__device__ __forceinline__ void ldsm4(uint32_t* r, uint32_t addr) {
    asm volatile("ldmatrix.sync.aligned.m8n8.x4.shared.b16 {%0,%1,%2,%3}, [%4];"
                 : "=r"(r[0]), "=r"(r[1]), "=r"(r[2]), "=r"(r[3]) : "r"(addr));
}
__device__ __forceinline__ void mma_f16(float* c, const uint32_t* a, const uint32_t* b) {
    asm volatile(
        "mma.sync.aligned.m16n8k16.row.col.f32.f16.f16.f32 "
        "{%0,%1,%2,%3}, {%4,%5,%6,%7}, {%8,%9}, {%0,%1,%2,%3};"
        : "+f"(c[0]), "+f"(c[1]), "+f"(c[2]), "+f"(c[3])
        : "r"(a[0]), "r"(a[1]), "r"(a[2]), "r"(a[3]), "r"(b[0]), "r"(b[1]));
}

__global__ void __launch_bounds__(256) gemm_k() {
    extern __shared__ uint8_t dsm_raw[];
    uint32_t base0 = (uint32_t)__cvta_generic_to_shared(dsm_raw);
    uint32_t sbase = (base0 + 1023) & ~1023u;

    int tid  = threadIdx.x;
    int lane = tid & 31;
    int wid  = tid >> 5;
    int g    = lane >> 2;
    int tig  = lane & 3;
    int wm   = (wid & 1) * 64;
    int wn   = (wid >> 1) * 32;
    int ntile = blockIdx.x, mtile = blockIdx.y;

    const __half* Agh = g_ls_hi + (size_t)(mtile * BM) * KD;
    const __half* Agl = g_ls_lo + (size_t)(mtile * BM) * KD;
    const __half* Bgh = g_B_hi  + (size_t)(ntile * BN) * KD;
    const __half* Bgl = g_B_lo  + (size_t)(ntile * BN) * KD;

    float c[4][4][4];
    #pragma unroll
    for (int mi = 0; mi < 4; ++mi)
        #pragma unroll
        for (int ni = 0; ni < 4; ++ni)
            #pragma unroll
            for (int q = 0; q < 4; ++q) c[mi][ni][q] = 0.0f;

    // Staging: 2048 16B-chunks/stage (A:1024, B:1024); row = [hi 4ch | lo 4ch]
    auto stage = [&](int it2, int s) {
        uint32_t base = sbase + (uint32_t)s * STAGE_B;
        int kb = it2 * BK;
        #pragma unroll
        for (int i = 0; i < 8; ++i) {
            int isB   = (i >= 4);
            int local = tid + i * 256 - isB * 1024;
            int row   = local >> 3;
            int ch    = local & 7;
            int hil   = ch >> 2;
            int ck    = ch & 3;
            const __half* src =
                (isB ? (hil ? Bgl : Bgh) + (size_t)row * KD
                     : (hil ? Agl : Agh) + (size_t)row * KD) + kb + ck * 8;
            uint32_t dst = base + (isB ? 16384u : 0u)
                         + (uint32_t)row * 128 + (uint32_t)((ch ^ (row & 7)) << 4);
            cp16s(dst, src);
        }
        asm volatile("cp.async.commit_group;");
    };

    stage(0, 0);

    for (int it = 0; it < NKIT; ++it) {
        int s = it & 1;
        if (it + 1 < NKIT) {
            stage(it + 1, s ^ 1);
            asm volatile("cp.async.wait_group 1;");
        } else {
            asm volatile("cp.async.wait_group 0;");
        }
        __syncthreads();

        uint32_t Ab = sbase + (uint32_t)s * STAGE_B;
        uint32_t Bb = Ab + 16384;

        #pragma unroll
        for (int ks = 0; ks < 2; ++ks) {
            uint32_t ah[4][4], al[4][4], bh[4][2], bl[4][2];
            #pragma unroll
            for (int mi = 0; mi < 4; ++mi) {
                int row = wm + mi * 16 + (lane & 15);
                int kc  = lane >> 4;
                ldsm4(ah[mi], Ab + row * 128 + (((ks * 2 + kc)     ^ (row & 7)) << 4));
                ldsm4(al[mi], Ab + row * 128 + (((4 + ks * 2 + kc) ^ (row & 7)) << 4));
            }
            #pragma unroll
            for (int p = 0; p < 2; ++p) {
                int row = wn + p * 16 + ((lane >> 4) & 1) * 8 + (lane & 7);
                int kc  = (lane >> 3) & 1;
                uint32_t r4[4];
                ldsm4(r4, Bb + row * 128 + (((ks * 2 + kc) ^ (row & 7)) << 4));
                bh[2*p][0] = r4[0]; bh[2*p][1] = r4[1];
                bh[2*p+1][0] = r4[2]; bh[2*p+1][1] = r4[3];
                ldsm4(r4, Bb + row * 128 + (((4 + ks * 2 + kc) ^ (row & 7)) << 4));
                bl[2*p][0] = r4[0]; bl[2*p][1] = r4[1];
                bl[2*p+1][0] = r4[2]; bl[2*p+1][1] = r4[3];
            }
            #pragma unroll
            for (int mi = 0; mi < 4; ++mi)
                #pragma unroll
                for (int ni = 0; ni < 4; ++ni) {
                    mma_f16(c[mi][ni], al[mi], bh[ni]);
                    mma_f16(c[mi][ni], ah[mi], bl[ni]);
                    mma_f16(c[mi][ni], ah[mi], bh[ni]);
                }
        }
        __syncthreads();
    }

    // Epilogue: direct float2 stores
    int rowbase = mtile * BM + wm;
    int colbase = ntile * BN + wn;
    #pragma unroll
    for (int mi = 0; mi < 4; ++mi) {
        #pragma unroll
        for (int ni = 0; ni < 4; ++ni) {
            int r0 = rowbase + mi * 16 + g;
            int cc = colbase + ni * 8 + tig * 2;
            *(float2*)&g_V[(size_t)r0 * NBP + cc] =
                make_float2(c[mi][ni][0], c[mi][ni][1]);
            *(float2*)&g_V[(size_t)(r0 + 8) * NBP + cc] =
                make_float2(c[mi][ni][2], c[mi][ni][3]);
        }
    }
}

// ---------------------------------------------------------------------------
// Kernel 3: RK4 scan. One CTA per batch element, 128 threads.
// ---------------------------------------------------------------------------
__global__ void __launch_bounds__(128) scan_k(
    const float* __restrict__ X,    const float* __restrict__ W_in,
    const float* __restrict__ b_in, const float* __restrict__ W1,
    const float* __restrict__ b1,   const float* __restrict__ W_out,
    const float* __restrict__ b_out, float* __restrict__ out)
{
    __shared__ float Vs[129 * 64];
    __shared__ float h[64], ht[64], z[128], ksum[64];

    int b = blockIdx.x;
    int t = threadIdx.x;

    float w1r[64];
    #pragma unroll
    for (int i = 0; i < 64; ++i) w1r[i] = W1[i * 128 + t];
    float b1t = b1[t];

    if (t < 64) {
        float acc = b_in[t];
        const float* x0 = X + (size_t)b * T_SZ * D_SZ;
        #pragma unroll
        for (int d = 0; d < 64; ++d) acc += x0[d] * W_in[d * 64 + t];
        h[t] = acc; ht[t] = acc; ksum[t] = 0.0f;
    }
    __syncthreads();

    const float wgt[4] = {1.0f, 2.0f, 2.0f, 1.0f};
    const float aco[4] = {0.5f, 0.5f, 1.0f, 0.0f};

    for (int n = 0; n < NI_SZ; ++n) {
        const float4* vg = (const float4*)(g_V + (size_t)(b * NI_SZ + n) * NBP);
        float4* vs4 = (float4*)Vs;
        for (int c4 = t; c4 < (129 * 64) / 4; c4 += 128) vs4[c4] = vg[c4];
        __syncthreads();

        #pragma unroll
        for (int s = 0; s < 4; ++s) {
            float acc = b1t;
            #pragma unroll
            for (int i = 0; i < 64; ++i) acc += ht[i] * w1r[i];
            z[t] = tanhf(acc);
            __syncthreads();
            if (t < 64) {
                float ka = Vs[128 * 64 + t];
                #pragma unroll
                for (int m = 0; m < 128; ++m) ka += z[m] * Vs[m * 64 + t];
                ksum[t] += wgt[s] * ka;
                if (s < 3) ht[t] = h[t] + aco[s] * ka;
            }
            __syncthreads();
        }
        if (t < 64) {
            float hn = h[t] + ksum[t] * (1.0f / 6.0f);
            h[t] = hn; ht[t] = hn; ksum[t] = 0.0f;
        }
        __syncthreads();
    }

    if (t < OUT_SZ) {
        float acc = b_out[t];
        #pragma unroll
        for (int d = 0; d < 64; ++d) acc += h[d] * W_out[d * OUT_SZ + t];
        out[b * OUT_SZ + t] = acc;
    }
}

// ---------------------------------------------------------------------------
extern "C" void kernel_launch(void* const* d_in, const int* in_sizes, int n_in,
                              void* d_out, int out_size) {
    const float* X     = (const float*)d_in[0];
    const float* W_in  = (const float*)d_in[1];
    const float* b_in  = (const float*)d_in[2];
    const float* W1    = (const float*)d_in[3];
    const float* b1    = (const float*)d_in[4];
    const float* W2    = (const float*)d_in[5];
    const float* b2    = (const float*)d_in[6];
    const float* W_out = (const float*)d_in[7];
    const float* b_out = (const float*)d_in[8];
    float* out = (float*)d_out;

    (void)in_sizes; (void)n_in; (void)out_size;

    int gemm_smem = 2 * STAGE_B + 1024;   // 66560
    cudaFuncSetAttribute(gemm_k, cudaFuncAttributeMaxDynamicSharedMemorySize, gemm_smem);

    prep_B_k<<<NBP, 128>>>(W2, b2);
    logsig_k<<<dim3(NI_SZ, B_SZ), 256>>>(X);
    gemm_k<<<dim3(NBP / BN, BN_TOT / BM), 256, gemm_smem>>>();
    scan_k<<<B_SZ, 128>>>(X, W_in, b_in, W1, b1, W_out, b_out, out);
}